// round 11
// baseline (speedup 1.0000x reference)
#include <cuda_runtime.h>
#include <cuda_fp16.h>
#include <cstdint>

// Problem dims
#define B   64
#define NN  2048
#define NC  32
#define IC  16
#define OC  32
#define KO  (NC * OC)      // 1024
#define NCHUNK 64          // blocks per batch for k_iter (128-thr blocks)
#define NPB (NN / NCHUNK)  // 32 nodes per block -> 8 per warp (4 warps)

// ---------------- scratch (device globals; no runtime allocation) ----------
__device__ __half g_priors[(size_t)B * NN * KO];   // 268 MB fp16 priors [b][n][k][o]
__device__ float  g_logits[(size_t)B * NN * NC];   // 16 MB  logits  [b][n][k]
__device__ float  g_s[B * KO];                     // s accumulator (zeroed by squash)
__device__ float  g_out[B * KO];                   // current outputs v_i

// ---------------- pass 0: priors = einsum('bni,nkio->bnko'), fp16 store ----
// One block per node n. W[n] (32x16x32 fp32 = 64KB) lives in registers,
// reused across all 64 batches. Packed f32x2 FMA doubles fp32 throughput.
__global__ void __launch_bounds__(256) k_priors(const float* __restrict__ x,
                                                const float* __restrict__ w) {
    const int n  = blockIdx.x;
    const int t  = threadIdx.x;
    const int k  = t >> 3;            // capsule 0..31
    const int og = (t & 7) * 4;       // out-channel group (4 consecutive o)

    // x packed as (v,v) f32x2 per element for broadcast FMA
    __shared__ unsigned long long sx[B][IC];   // 8 KB

    for (int idx = t; idx < B * IC; idx += 256) {
        int b = idx >> 4, i = idx & 15;
        float v = x[((size_t)b * NN + n) * IC + i];
        unsigned long long pv;
        asm("mov.b64 %0, {%1, %2};" : "=l"(pv) : "f"(v), "f"(v));
        sx[b][i] = pv;
    }

    // Load this thread's W slice: W[n][k][0..15][og..og+3] -> 32 packed pairs
    unsigned long long wp[2 * IC];
    const float* wbase = w + (((size_t)n * NC + k) * IC) * OC + og;
#pragma unroll
    for (int i = 0; i < IC; i++) {
        ulonglong2 v = *(const ulonglong2*)(wbase + (size_t)i * OC);
        wp[2 * i]     = v.x;   // (w[og],   w[og+1])
        wp[2 * i + 1] = v.y;   // (w[og+2], w[og+3])
    }
    __syncthreads();

    __half* pout = g_priors + (size_t)n * KO + (size_t)k * OC + og;
#pragma unroll 1
    for (int b = 0; b < B; b++) {
        unsigned long long a0 = 0ull, a1 = 0ull;
#pragma unroll
        for (int i = 0; i < IC; i++) {
            unsigned long long xv = sx[b][i];
            asm("fma.rn.f32x2 %0, %1, %2, %0;" : "+l"(a0) : "l"(xv), "l"(wp[2 * i]));
            asm("fma.rn.f32x2 %0, %1, %2, %0;" : "+l"(a1) : "l"(xv), "l"(wp[2 * i + 1]));
        }
        float f0, f1, f2, f3;
        asm("mov.b64 {%0, %1}, %2;" : "=f"(f0), "=f"(f1) : "l"(a0));
        asm("mov.b64 {%0, %1}, %2;" : "=f"(f2), "=f"(f3) : "l"(a1));
        __half2 h01 = __floats2half2_rn(f0, f1);
        __half2 h23 = __floats2half2_rn(f2, f3);
        uint2 st;
        st.x = *(const unsigned int*)&h01;
        st.y = *(const unsigned int*)&h23;
        *(uint2*)(pout + (size_t)b * NN * KO) = st;
    }
}

// ---------------- routing pass (fused delta + softmax + weighted sum) ------
// Grid: (NCHUNK, B), 128-thread CTAs, 4 CTAs/SM = 16 warps. One warp per node
// round: lane = capsule k. DEPTH-2 register pipeline: each warp keeps TWO full
// node-rows (4KB) in flight -> 64KB outstanding/SM, covering the ~1000-cycle
// loaded DRAM latency at the SM's BW share (the R10 measurement showed DRAM%
// scales with in-flight bytes).
// Softmax WITHOUT max-subtraction: logits bounded (||out|| < 1 from squash).
// ITER==0 walks nodes in REVERSE (tail of k_priors' stream still in L2).
template <int ITER>
__global__ void __launch_bounds__(128, 4) k_iter() {
    const int b    = blockIdx.y;
    const int warp = threadIdx.x >> 5;     // 0..3
    const int lane = threadIdx.x & 31;     // capsule index k

    __shared__ float   s_s[NC * 33];       // padded: bank-conflict-free
    __shared__ __half2 s_outh[NC][17];     // out row as half2 pairs, padded

    for (int idx = threadIdx.x; idx < NC * 33; idx += 128) s_s[idx] = 0.f;
    if (ITER > 0) {
        const float2* op = (const float2*)g_out + b * (KO / 2);
        for (int idx = threadIdx.x; idx < KO / 2; idx += 128) {
            int k = idx >> 4, r = idx & 15;
            s_outh[k][r] = __float22half2_rn(op[idx]);
        }
    }
    __syncthreads();

    float acc[OC];
#pragma unroll
    for (int j = 0; j < OC; j++) acc[j] = 0.f;

    const int n0 = blockIdx.x * NPB;
    const __half* base  = g_priors + ((size_t)b * NN + n0) * KO + (size_t)lane * OC;
    const float*  lbase = g_logits + ((size_t)b * NN + n0) * NC + lane;

    // address-only node remap: ITER 0 consumes nodes in reverse order
#define IDX(v) ((ITER == 0) ? (NPB - 1 - (v)) : (v))

    // prologue: load nodes (warp) and (warp+4) -> two buffers in flight
    uint4 u0[4], u1[4];
    {
        const uint4* rp = (const uint4*)(base + (size_t)IDX(warp) * KO);
#pragma unroll
        for (int q = 0; q < 4; q++) u0[q] = rp[q];
    }
    {
        int p1 = (warp + 4 < NPB) ? warp + 4 : warp;
        const uint4* rp = (const uint4*)(base + (size_t)IDX(p1) * KO);
#pragma unroll
        for (int q = 0; q < 4; q++) u1[q] = rp[q];
    }
    float lg0 = 0.f, lg1 = 0.f;
    if (ITER == 2) {
        lg0 = lbase[IDX(warp) * NC];
        int p1 = (warp + 4 < NPB) ? warp + 4 : warp;
        lg1 = lbase[IDX(p1) * NC];
    }

#pragma unroll 1
    for (int nn = warp; nn < NPB; nn += 4) {
        // ---- issue load for node nn+8 (depth-2) ----
        const int pn = (nn + 8 < NPB) ? nn + 8 : nn;
        uint4 u2[4];
        {
            const uint4* rp = (const uint4*)(base + (size_t)IDX(pn) * KO);
#pragma unroll
            for (int q = 0; q < 4; q++) u2[q] = rp[q];
        }
        float lg2 = 0.f;
        if (ITER == 2) lg2 = lbase[IDX(pn) * NC];

        // ---- compute on current node (u0) ----
        const __half2* ph = (const __half2*)u0;   // 16 half2 = 32 o-values
        float prob;
        if (ITER == 0) {
            prob = 1.0f / NC;
        } else {
            // delta = dot(p, out[k]) via 4 independent HFMA2 chains
            __half2 dh0 = __float2half2_rn(0.f), dh1 = dh0, dh2 = dh0, dh3 = dh0;
#pragma unroll
            for (int r = 0; r < 16; r += 4) {
                dh0 = __hfma2(ph[r + 0], s_outh[lane][r + 0], dh0);
                dh1 = __hfma2(ph[r + 1], s_outh[lane][r + 1], dh1);
                dh2 = __hfma2(ph[r + 2], s_outh[lane][r + 2], dh2);
                dh3 = __hfma2(ph[r + 3], s_outh[lane][r + 3], dh3);
            }
            float2 f0 = __half22float2(__hadd2(dh0, dh1));
            float2 f1 = __half22float2(__hadd2(dh2, dh3));
            float d = (f0.x + f0.y) + (f1.x + f1.y);

            float logit = d;
            if (ITER == 2) logit += lg0;
            if (ITER == 1)
                g_logits[((size_t)b * NN + n0 + nn) * NC + lane] = d;

            // softmax across 32 lanes, no max-subtraction (bounded logits)
            float e = __expf(logit);
            float se = e;
#pragma unroll
            for (int off = 16; off > 0; off >>= 1)
                se += __shfl_xor_sync(0xffffffffu, se, off);
            prob = __fdividef(e, se);
        }

#pragma unroll
        for (int r = 0; r < 16; r++) {
            float2 pf2 = __half22float2(ph[r]);
            acc[2 * r]     = fmaf(prob, pf2.x, acc[2 * r]);
            acc[2 * r + 1] = fmaf(prob, pf2.y, acc[2 * r + 1]);
        }

        // ---- rotate pipeline: u0 <- u1 <- u2 ----
#pragma unroll
        for (int q = 0; q < 4; q++) { u0[q] = u1[q]; u1[q] = u2[q]; }
        lg0 = lg1; lg1 = lg2;
    }
#undef IDX

    // per-warp accumulators -> shared (conflict-free: 33-stride rows)
#pragma unroll
    for (int j = 0; j < OC; j++) atomicAdd(&s_s[lane * 33 + j], acc[j]);
    __syncthreads();

    for (int idx = threadIdx.x; idx < KO; idx += 128)
        atomicAdd(&g_s[b * KO + idx], s_s[(idx >> 5) * 33 + (idx & 31)]);
}

// ---------------- squash: v = (|s|^2/(1+|s|^2)) * s/|s| -------------------
// Grid: (NC, B), 32 threads (lane = o). Also re-zeros g_s so the next pass /
// next graph replay starts clean (keeps kernel_launch deterministic).
template <bool FINAL>
__global__ void k_squash(float* __restrict__ dst) {
    const int k = blockIdx.x, b = blockIdx.y, o = threadIdx.x;
    const int idx = b * KO + k * OC + o;
    float v = g_s[idx];
    g_s[idx] = 0.f;
    float sq = v * v;
#pragma unroll
    for (int off = 16; off > 0; off >>= 1)
        sq += __shfl_xor_sync(0xffffffffu, sq, off);
    float scale = sqrtf(sq) / (1.f + sq);   // = (sq/(1+sq)) / sqrt(sq)
    float out = v * scale;
    if (FINAL) dst[idx] = out;
    else       g_out[idx] = out;
}

// ---------------- launch ----------------------------------------------------
extern "C" void kernel_launch(void* const* d_in, const int* in_sizes, int n_in,
                              void* d_out, int out_size) {
    const float* x = (const float*)d_in[0];          // [B, NN, IC]
    const float* w = (const float*)d_in[1];          // [NN, NC, IC, OC]
    float* out = (float*)d_out;                      // [B, 1, NC, OC]

    k_priors<<<NN, 256>>>(x, w);

    k_iter<0><<<dim3(NCHUNK, B), 128>>>();
    k_squash<false><<<dim3(NC, B), 32>>>(nullptr);

    k_iter<1><<<dim3(NCHUNK, B), 128>>>();
    k_squash<false><<<dim3(NC, B), 32>>>(nullptr);

    k_iter<2><<<dim3(NCHUNK, B), 128>>>();
    k_squash<true><<<dim3(NC, B), 32>>>(out);
}

// round 12
// speedup vs baseline: 1.1465x; 1.1465x over previous
#include <cuda_runtime.h>
#include <cuda_fp16.h>
#include <cstdint>

// Problem dims
#define B   64
#define NN  2048
#define NC  32
#define IC  16
#define OC  32
#define KO  (NC * OC)      // 1024
#define NCHUNK 32          // blocks per batch for k_iter (128-thr blocks)
#define NPB (NN / NCHUNK)  // 64 nodes per block -> 16 rounds per warp
#define ROUNDS (NPB / 4)   // 16

// ---------------- scratch (device globals; no runtime allocation) ----------
__device__ __half g_priors[(size_t)B * NN * KO];   // 268 MB fp16 priors [b][n][k][o]
__device__ float  g_logits[(size_t)B * NN * NC];   // 16 MB  logits  [b][n][k]
__device__ float  g_s[B * KO];                     // s accumulator (zeroed by squash)
__device__ float  g_out[B * KO];                   // current outputs v_i

// ---------------- pass 0: priors = einsum('bni,nkio->bnko'), fp16 store ----
// One block per node n. W[n] (32x16x32 fp32 = 64KB) lives in registers,
// reused across all 64 batches. Packed f32x2 FMA doubles fp32 throughput.
__global__ void __launch_bounds__(256) k_priors(const float* __restrict__ x,
                                                const float* __restrict__ w) {
    const int n  = blockIdx.x;
    const int t  = threadIdx.x;
    const int k  = t >> 3;            // capsule 0..31
    const int og = (t & 7) * 4;       // out-channel group (4 consecutive o)

    // x packed as (v,v) f32x2 per element for broadcast FMA
    __shared__ unsigned long long sx[B][IC];   // 8 KB

    for (int idx = t; idx < B * IC; idx += 256) {
        int b = idx >> 4, i = idx & 15;
        float v = x[((size_t)b * NN + n) * IC + i];
        unsigned long long pv;
        asm("mov.b64 %0, {%1, %2};" : "=l"(pv) : "f"(v), "f"(v));
        sx[b][i] = pv;
    }

    // Load this thread's W slice: W[n][k][0..15][og..og+3] -> 32 packed pairs
    unsigned long long wp[2 * IC];
    const float* wbase = w + (((size_t)n * NC + k) * IC) * OC + og;
#pragma unroll
    for (int i = 0; i < IC; i++) {
        ulonglong2 v = *(const ulonglong2*)(wbase + (size_t)i * OC);
        wp[2 * i]     = v.x;   // (w[og],   w[og+1])
        wp[2 * i + 1] = v.y;   // (w[og+2], w[og+3])
    }
    __syncthreads();

    __half* pout = g_priors + (size_t)n * KO + (size_t)k * OC + og;
#pragma unroll 1
    for (int b = 0; b < B; b++) {
        unsigned long long a0 = 0ull, a1 = 0ull;
#pragma unroll
        for (int i = 0; i < IC; i++) {
            unsigned long long xv = sx[b][i];
            asm("fma.rn.f32x2 %0, %1, %2, %0;" : "+l"(a0) : "l"(xv), "l"(wp[2 * i]));
            asm("fma.rn.f32x2 %0, %1, %2, %0;" : "+l"(a1) : "l"(xv), "l"(wp[2 * i + 1]));
        }
        float f0, f1, f2, f3;
        asm("mov.b64 {%0, %1}, %2;" : "=f"(f0), "=f"(f1) : "l"(a0));
        asm("mov.b64 {%0, %1}, %2;" : "=f"(f2), "=f"(f3) : "l"(a1));
        __half2 h01 = __floats2half2_rn(f0, f1);
        __half2 h23 = __floats2half2_rn(f2, f3);
        uint2 st;
        st.x = *(const unsigned int*)&h01;
        st.y = *(const unsigned int*)&h23;
        *(uint2*)(pout + (size_t)b * NN * KO) = st;
    }
}

// ---------------- routing pass (fused delta + softmax + weighted sum) ------
// Grid: (NCHUNK, B), 128-thread CTAs, 4 CTAs/SM = 16 warps. lane = capsule k.
// TRUE depth-2 pipeline: the 16-round node loop is fully unrolled over a
// 3-buffer rotating array (static indices after unroll -> no register copies,
// no early scoreboard waits; round r depends only on the load issued at round
// r-2). 16 warps x 4KB genuinely in flight = 64KB/SM.
// Softmax WITHOUT max-subtraction: logits bounded (||out|| < 1 from squash).
// ITER==0 walks nodes in REVERSE (tail of k_priors' stream still in L2).
template <int ITER>
__global__ void __launch_bounds__(128, 4) k_iter() {
    const int b    = blockIdx.y;
    const int warp = threadIdx.x >> 5;     // 0..3
    const int lane = threadIdx.x & 31;     // capsule index k

    __shared__ float   s_s[NC * 33];       // padded: bank-conflict-free
    __shared__ __half2 s_outh[NC][17];     // out row as half2 pairs, padded

    for (int idx = threadIdx.x; idx < NC * 33; idx += 128) s_s[idx] = 0.f;
    if (ITER > 0) {
        const float2* op = (const float2*)g_out + b * (KO / 2);
        for (int idx = threadIdx.x; idx < KO / 2; idx += 128) {
            int k = idx >> 4, r = idx & 15;
            s_outh[k][r] = __float22half2_rn(op[idx]);
        }
    }
    __syncthreads();

    float acc[OC];
#pragma unroll
    for (int j = 0; j < OC; j++) acc[j] = 0.f;

    const int n0 = blockIdx.x * NPB;
    const __half* base  = g_priors + ((size_t)b * NN + n0) * KO + (size_t)lane * OC;
    const float*  lbase = g_logits + ((size_t)b * NN + n0) * NC + lane;

    // address-only node remap: ITER 0 consumes nodes in reverse order
#define IDX(v) ((ITER == 0) ? (NPB - 1 - (v)) : (v))

    uint4 ub[3][4];                        // 3 rotating 64B buffers
    float lg[3];
    lg[0] = lg[1] = lg[2] = 0.f;

    // prologue: issue loads for rounds 0 and 1 (ROUNDS=16 >= 2 always)
#pragma unroll
    for (int s = 0; s < 2; s++) {
        const int node = warp + 4 * s;
        const uint4* rp = (const uint4*)(base + (size_t)IDX(node) * KO);
#pragma unroll
        for (int q = 0; q < 4; q++) ub[s][q] = rp[q];
        if (ITER == 2) lg[s] = lbase[IDX(node) * NC];
    }

#pragma unroll
    for (int r = 0; r < ROUNDS; r++) {
        const int nn = warp + 4 * r;

        // ---- issue load for round r+2 into buffer (r+2)%3 (static idx) ----
        if (r + 2 < ROUNDS) {
            const int pnode = warp + 4 * (r + 2);
            const uint4* rp = (const uint4*)(base + (size_t)IDX(pnode) * KO);
#pragma unroll
            for (int q = 0; q < 4; q++) ub[(r + 2) % 3][q] = rp[q];
            if (ITER == 2) lg[(r + 2) % 3] = lbase[IDX(pnode) * NC];
        }

        // ---- compute on round r from buffer r%3 ----
        const __half2* ph = (const __half2*)ub[r % 3];   // 16 half2 = 32 o
        float prob;
        if (ITER == 0) {
            prob = 1.0f / NC;
        } else {
            // delta = dot(p, out[k]) via 4 independent HFMA2 chains
            __half2 dh0 = __float2half2_rn(0.f), dh1 = dh0, dh2 = dh0, dh3 = dh0;
#pragma unroll
            for (int q = 0; q < 16; q += 4) {
                dh0 = __hfma2(ph[q + 0], s_outh[lane][q + 0], dh0);
                dh1 = __hfma2(ph[q + 1], s_outh[lane][q + 1], dh1);
                dh2 = __hfma2(ph[q + 2], s_outh[lane][q + 2], dh2);
                dh3 = __hfma2(ph[q + 3], s_outh[lane][q + 3], dh3);
            }
            float2 f0 = __half22float2(__hadd2(dh0, dh1));
            float2 f1 = __half22float2(__hadd2(dh2, dh3));
            float d = (f0.x + f0.y) + (f1.x + f1.y);

            float logit = d;
            if (ITER == 2) logit += lg[r % 3];
            if (ITER == 1)
                g_logits[((size_t)b * NN + n0 + nn) * NC + lane] = d;

            // softmax across 32 lanes, no max-subtraction (bounded logits)
            float e = __expf(logit);
            float se = e;
#pragma unroll
            for (int off = 16; off > 0; off >>= 1)
                se += __shfl_xor_sync(0xffffffffu, se, off);
            prob = __fdividef(e, se);
        }

#pragma unroll
        for (int q = 0; q < 16; q++) {
            float2 pf2 = __half22float2(ph[q]);
            acc[2 * q]     = fmaf(prob, pf2.x, acc[2 * q]);
            acc[2 * q + 1] = fmaf(prob, pf2.y, acc[2 * q + 1]);
        }
    }
#undef IDX

    // per-warp accumulators -> shared (conflict-free: 33-stride rows)
#pragma unroll
    for (int j = 0; j < OC; j++) atomicAdd(&s_s[lane * 33 + j], acc[j]);
    __syncthreads();

    for (int idx = threadIdx.x; idx < KO; idx += 128)
        atomicAdd(&g_s[b * KO + idx], s_s[(idx >> 5) * 33 + (idx & 31)]);
}

// ---------------- squash: v = (|s|^2/(1+|s|^2)) * s/|s| -------------------
// Grid: (NC, B), 32 threads (lane = o). Also re-zeros g_s so the next pass /
// next graph replay starts clean (keeps kernel_launch deterministic).
template <bool FINAL>
__global__ void k_squash(float* __restrict__ dst) {
    const int k = blockIdx.x, b = blockIdx.y, o = threadIdx.x;
    const int idx = b * KO + k * OC + o;
    float v = g_s[idx];
    g_s[idx] = 0.f;
    float sq = v * v;
#pragma unroll
    for (int off = 16; off > 0; off >>= 1)
        sq += __shfl_xor_sync(0xffffffffu, sq, off);
    float scale = sqrtf(sq) / (1.f + sq);   // = (sq/(1+sq)) / sqrt(sq)
    float out = v * scale;
    if (FINAL) dst[idx] = out;
    else       g_out[idx] = out;
}

// ---------------- launch ----------------------------------------------------
extern "C" void kernel_launch(void* const* d_in, const int* in_sizes, int n_in,
                              void* d_out, int out_size) {
    const float* x = (const float*)d_in[0];          // [B, NN, IC]
    const float* w = (const float*)d_in[1];          // [NN, NC, IC, OC]
    float* out = (float*)d_out;                      // [B, 1, NC, OC]

    k_priors<<<NN, 256>>>(x, w);

    k_iter<0><<<dim3(NCHUNK, B), 128>>>();
    k_squash<false><<<dim3(NC, B), 32>>>(nullptr);

    k_iter<1><<<dim3(NCHUNK, B), 128>>>();
    k_squash<false><<<dim3(NC, B), 32>>>(nullptr);

    k_iter<2><<<dim3(NCHUNK, B), 128>>>();
    k_squash<true><<<dim3(NC, B), 32>>>(out);
}